// round 16
// baseline (speedup 1.0000x reference)
#include <cuda_runtime.h>
#include <cuda_fp16.h>

#define DIM    192
#define HEADS  6
#define NTOK   49
#define NWIN   64
#define BMS    50
#define NTHR   256      // 8 warps, 3 CTAs/SM
#define NWINDOWS 4096
#define GRID   444      // 148 SMs x 3 CTAs, persistent

#define NKB    12
#define XS_U   (NKB*4*128)     // 6144
#define KS_U   (NKB*7*64)      // 5376
#define VS_U   (4*24*64)       // 6144
#define SM_U   (XS_U + KS_U + VS_U)    // 17664 u32 = 70,656 B

__device__ unsigned g_Wh[12*72*32*2];            // qkv_w fp16, B-frag pair-packed (Q rows pre-scaled)
__device__ unsigned g_Ph[12*24*32*2];            // proj_w fp16, B-frag pair-packed
__device__ float    g_qb[576];                   // qkv_b with Q part pre-scaled
__device__ float    g_bm[NWIN*HEADS*NTOK*BMS];   // bias+mask combined (fp32)

__device__ __forceinline__ unsigned f2h2(float x, float y) {
    __half2 h = __floats2half2_rn(x, y);
    return *(unsigned*)&h;
}

__device__ __forceinline__ void mmaf16(float d[4], const unsigned a[4], const unsigned b[2]) {
    asm volatile(
        "mma.sync.aligned.m16n8k16.row.col.f32.f16.f16.f32 "
        "{%0,%1,%2,%3}, {%4,%5,%6,%7}, {%8,%9}, {%0,%1,%2,%3};\n"
        : "+f"(d[0]), "+f"(d[1]), "+f"(d[2]), "+f"(d[3])
        : "r"(a[0]), "r"(a[1]), "r"(a[2]), "r"(a[3]), "r"(b[0]), "r"(b[1]));
}

__device__ __forceinline__ void ldsm_x4(unsigned a[4], const unsigned* p) {
    unsigned addr = (unsigned)__cvta_generic_to_shared(p);
    asm volatile("ldmatrix.sync.aligned.m8n8.x4.shared.b16 {%0,%1,%2,%3}, [%4];"
                 : "=r"(a[0]), "=r"(a[1]), "=r"(a[2]), "=r"(a[3]) : "r"(addr));
}
__device__ __forceinline__ void ldsm_x2(unsigned b[2], const unsigned* p) {
    unsigned addr = (unsigned)__cvta_generic_to_shared(p);
    asm volatile("ldmatrix.sync.aligned.m8n8.x2.shared.b16 {%0,%1}, [%2];"
                 : "=r"(b[0]), "=r"(b[1]) : "r"(addr));
}

// A block layout: unit u = ((col>>3)&1)*16 + (row&15), 16B contiguous in k.
__device__ __forceinline__ void a_load(const unsigned* base, int kblk, int mt, int lane, unsigned a[4]) {
    ldsm_x4(a, base + (kblk*4 + mt)*128 + lane*4);
}
__device__ __forceinline__ void a_store(unsigned* base, int row, int col, unsigned h2) {
    base[((col >> 4)*4 + (row >> 4))*128
         + (((col >> 3) & 1)*16 + (row & 15))*4 + ((col >> 1) & 3)] = h2;
}
// B block layout: unit u = ((k>>3)&1)*8 + (n&7).
__device__ __forceinline__ void b_load(const unsigned* base, int NT, int kblk, int nt, int lane, unsigned b[2]) {
    ldsm_x2(b, base + (kblk*NT + nt)*64 + (lane & 15)*4);
}
__device__ __forceinline__ void b_load2(const unsigned* base, int NT, int kblk, int nt, int lane, unsigned b4[4]) {
    ldsm_x4(b4, base + (kblk*NT + nt)*64 + lane*4);
}
__device__ __forceinline__ int b_slot(int NT, int kblk, int nt, int k, int n) {
    return (kblk*NT + nt)*64 + (((k >> 3) & 1)*8 + (n & 7))*4 + ((k >> 1) & 3);
}

// ---------------- prep kernel ----------------
__global__ void prep_kernel(const float* __restrict__ qkv_w,
                            const float* __restrict__ proj_w,
                            const float* __restrict__ qkv_b,
                            const float* __restrict__ bias_table,
                            const int*   __restrict__ rel_idx,
                            const float* __restrict__ mask)
{
    const float scale = 0.17677669529663687f;   // 32^-0.5, folded into Q weights
    const int NWE = 96*576, NPE = 96*192, NBE = NWIN*HEADS*NTOK*NTOK;
    for (int idx = blockIdx.x*blockDim.x + threadIdx.x;
         idx < NWE + NPE + NBE + 576; idx += gridDim.x*blockDim.x) {
        if (idx < NWE) {
            int kp = idx / 576, n = idx % 576;
            int k = 2*kp;
            float m = (n < 192) ? scale : 1.f;
            int s = (((k >> 4)*72 + (n >> 3))*32 + ((n & 7)*4 + ((k >> 1) & 3)))*2
                    + ((k >> 3) & 1);
            g_Wh[s] = f2h2(qkv_w[n*192 + k]*m, qkv_w[n*192 + k + 1]*m);
        } else if (idx < NWE + NPE) {
            int t = idx - NWE;
            int kp = t / 192, n = t % 192;
            int k = 2*kp;
            int s = (((k >> 4)*24 + (n >> 3))*32 + ((n & 7)*4 + ((k >> 1) & 3)))*2
                    + ((k >> 3) & 1);
            g_Ph[s] = f2h2(proj_w[n*192 + k], proj_w[n*192 + k + 1]);
        } else if (idx < NWE + NPE + NBE) {
            int t = idx - NWE - NPE;
            int win = t / (HEADS*NTOK*NTOK);
            int r   = t % (HEADS*NTOK*NTOK);
            int h = r / (NTOK*NTOK);
            int e = r % (NTOK*NTOK);
            int i = e / NTOK, j = e % NTOK;
            g_bm[((win*HEADS + h)*NTOK + i)*BMS + j] =
                bias_table[rel_idx[e]*HEADS + h] + mask[win*(NTOK*NTOK) + e];
        } else {
            int j = idx - NWE - NPE - NBE;
            g_qb[j] = qkv_b[j] * ((j < 192) ? scale : 1.f);
        }
    }
}

// ---------------- main kernel (persistent) ----------------
__global__ __launch_bounds__(NTHR, 3)
void win_attn15(const float* __restrict__ x,
                const float* __restrict__ proj_b,
                float* __restrict__ out)
{
    extern __shared__ unsigned smu[];
    unsigned* xs = smu;                 // A-pack: x -> Q (in place) -> attn-out (in place)
    unsigned* ks = xs + XS_U;           // B-pack K (tokens as n)
    unsigned* vs = ks + KS_U;           // B-pack V (tokens as k)

    const int tid  = threadIdx.x;
    const int w    = tid >> 5;
    const int lane = tid & 31;
    const int g    = lane >> 2;
    const int tig  = lane & 3;

    // V-pad zeroing once: tokens 56-63 never written inside the loop
    for (int p = tid; p < 768; p += NTHR) {
        int cblk = p >> 5;
        int rest = p & 31;
        vs[(3*24 + cblk)*64 + (8 + (rest >> 2))*4 + (rest & 3)] = 0u;
    }
    // (no sync needed yet: vs pad not read until attention, after many barriers)

    #pragma unroll 1
    for (int b = blockIdx.x; b < NWINDOWS; b += GRID) {

        // xs pad rows re-zeroed each window (AV wrote garbage rows 49-63 last iter)
        for (int p = tid; p < 15*96; p += NTHR) {
            int row = 49 + p/96, cp = p%96;
            a_store(xs, row, 2*cp, 0u);
        }
        const float2* xg = (const float2*)(x + (size_t)b * (NTOK*DIM));
        for (int p = tid; p < NTOK*96; p += NTHR) {
            int row = p / 96, cp = p % 96;
            float2 v = xg[p];
            a_store(xs, row, 2*cp, f2h2(v.x, v.y));
        }
        __syncthreads();

        // ---- QKV GEMM: 3 passes (K, V, Q), 4mt x 3nt; B double-buffered ----
        for (int pass = 0; pass < 3; pass++) {
            const int t0 = (pass == 0) ? 24 + w*3 : (pass == 1) ? 48 + w*3 : w*3;
            float acc[4][3][4];
            #pragma unroll
            for (int mt = 0; mt < 4; mt++)
                #pragma unroll
                for (int j = 0; j < 3; j++)
                    #pragma unroll
                    for (int e = 0; e < 4; e++) acc[mt][j][e] = 0.f;

            uint2 bb[3];
            #pragma unroll
            for (int j = 0; j < 3; j++)
                bb[j] = __ldg((const uint2*)g_Wh + (0*72 + t0 + j)*32 + lane);

            #pragma unroll
            for (int kk = 0; kk < NKB; kk++) {
                uint2 nb[3];
                if (kk + 1 < NKB) {
                    #pragma unroll
                    for (int j = 0; j < 3; j++)
                        nb[j] = __ldg((const uint2*)g_Wh + ((kk+1)*72 + t0 + j)*32 + lane);
                }
                unsigned a4[4][4];
                #pragma unroll
                for (int mt = 0; mt < 4; mt++) a_load(xs, kk, mt, lane, a4[mt]);
                #pragma unroll
                for (int j = 0; j < 3; j++) {
                    unsigned bArr[2] = {bb[j].x, bb[j].y};
                    #pragma unroll
                    for (int mt = 0; mt < 4; mt++) mmaf16(acc[mt][j], a4[mt], bArr);
                }
                #pragma unroll
                for (int j = 0; j < 3; j++) bb[j] = nb[j];
            }

            if (pass == 2) __syncthreads();   // all x reads done before Q overwrites xs

            #pragma unroll
            for (int j = 0; j < 3; j++) {
                const int j0 = (t0 + j)*8 + 2*tig;
                const float bj0 = __ldg(g_qb + j0);
                const float bj1 = __ldg(g_qb + j0 + 1);
                #pragma unroll
                for (int mt = 0; mt < 4; mt++) {
                    #pragma unroll
                    for (int hf = 0; hf < 2; hf++) {
                        float v0 = acc[mt][j][hf*2+0] + bj0;
                        float v1 = acc[mt][j][hf*2+1] + bj1;
                        if (pass == 0) {            // K: B[kdim][token]
                            const int token = mt*16 + g + 8*hf;
                            if (token < 56) {
                                const int kd = j0 - 192;
                                ks[b_slot(7, kd >> 4, token >> 3, kd, token)] = f2h2(v0, v1);
                            }
                        } else if (pass == 1) {     // V — pair-transpose via shfl
                            unsigned my = f2h2(v0, v1);
                            unsigned pt = __shfl_xor_sync(0xffffffffu, my, 4);
                            unsigned h2 = (g & 1) ? ((pt >> 16) | (my & 0xFFFF0000u))
                                                  : ((my & 0xFFFFu) | (pt << 16));
                            const int n   = (j0 - 384) + (g & 1);
                            const int tok = mt*16 + g + 8*hf;
                            if (tok < 56)
                                vs[b_slot(24, tok >> 4, n >> 3, tok, n)] = h2;
                        } else {                    // Q (pre-scaled) into xs in place
                            a_store(xs, mt*16 + g + 8*hf, j0, f2h2(v0, v1));
                        }
                    }
                }
            }
        }
        __syncthreads();

        // ---- attention: 24 tasks (head x 16-row quarter), 3 per warp; rolled ----
        {
            #pragma unroll 1
            for (int it = 0; it < 3; it++) {
                const int t = w + it*8;
                const int h = t >> 2;
                const int q = t & 3;

                float sc[7][4];
                #pragma unroll
                for (int nt = 0; nt < 7; nt++)
                    #pragma unroll
                    for (int e = 0; e < 4; e++) sc[nt][e] = 0.f;

                // QK^T with paired-x4 K loads
                {
                    const int kb0 = 2*h, kb1 = 2*h + 1;
                    unsigned qa0[4], qa1[4];
                    unsigned kf[7][2];
                    a_load(xs, kb0, q, lane, qa0);
                    b_load2(ks, 7, kb0, 0, lane, &kf[0][0]);
                    b_load2(ks, 7, kb0, 2, lane, &kf[2][0]);
                    b_load2(ks, 7, kb0, 4, lane, &kf[4][0]);
                    b_load (ks, 7, kb0, 6, lane, kf[6]);
                    a_load(xs, kb1, q, lane, qa1);
                    #pragma unroll
                    for (int nt = 0; nt < 7; nt++) mmaf16(sc[nt], qa0, kf[nt]);
                    b_load2(ks, 7, kb1, 0, lane, &kf[0][0]);
                    b_load2(ks, 7, kb1, 2, lane, &kf[2][0]);
                    b_load2(ks, 7, kb1, 4, lane, &kf[4][0]);
                    b_load (ks, 7, kb1, 6, lane, kf[6]);
                    #pragma unroll
                    for (int nt = 0; nt < 7; nt++) mmaf16(sc[nt], qa1, kf[nt]);
                }

                // add bias+mask, pad -> -1e30
                const float2* bmp = (const float2*)(g_bm
                                  + (size_t)((b & (NWIN-1))*HEADS + h) * NTOK * BMS);
                const int i0 = q*16 + g;
                #pragma unroll
                for (int nt = 0; nt < 7; nt++) {
                    const int j0 = nt*8 + 2*tig;
                    float2 u0 = make_float2(0.f, 0.f), u1 = u0;
                    if (i0 < NTOK && j0 < NTOK)   u0 = __ldg(bmp + (i0*BMS + j0)/2);
                    if (i0+8 < NTOK && j0 < NTOK) u1 = __ldg(bmp + ((i0+8)*BMS + j0)/2);
                    sc[nt][0] = (i0   < NTOK && j0   < NTOK) ? sc[nt][0] + u0.x : -1e30f;
                    sc[nt][1] = (i0   < NTOK && j0+1 < NTOK) ? sc[nt][1] + u0.y : -1e30f;
                    sc[nt][2] = (i0+8 < NTOK && j0   < NTOK) ? sc[nt][2] + u1.x : -1e30f;
                    sc[nt][3] = (i0+8 < NTOK && j0+1 < NTOK) ? sc[nt][3] + u1.y : -1e30f;
                }

                // softmax: exp + sum only; normalization deferred to AV output
                float inv0, inv1;
                #pragma unroll
                for (int hf = 0; hf < 2; hf++) {
                    float m = -1e30f;
                    #pragma unroll
                    for (int nt = 0; nt < 7; nt++) {
                        m = fmaxf(m, sc[nt][hf*2+0]);
                        m = fmaxf(m, sc[nt][hf*2+1]);
                    }
                    m = fmaxf(m, __shfl_xor_sync(0xffffffffu, m, 1));
                    m = fmaxf(m, __shfl_xor_sync(0xffffffffu, m, 2));
                    float s = 0.f;
                    #pragma unroll
                    for (int nt = 0; nt < 7; nt++) {
                        float e0 = __expf(sc[nt][hf*2+0] - m);
                        float e1 = __expf(sc[nt][hf*2+1] - m);
                        sc[nt][hf*2+0] = e0; sc[nt][hf*2+1] = e1;
                        s += e0 + e1;
                    }
                    s += __shfl_xor_sync(0xffffffffu, s, 1);
                    s += __shfl_xor_sync(0xffffffffu, s, 2);
                    if (hf == 0) inv0 = __frcp_rn(s); else inv1 = __frcp_rn(s);
                }

                // AV with UNNORMALIZED P (C-frags ARE the A-frags)
                float o[4][4];
                #pragma unroll
                for (int nv = 0; nv < 4; nv++)
                    #pragma unroll
                    for (int e = 0; e < 4; e++) o[nv][e] = 0.f;

                #pragma unroll
                for (int kb = 0; kb < 4; kb++) {
                    unsigned vf[8];
                    b_load2(vs, 24, kb, 4*h + 0, lane, vf + 0);
                    b_load2(vs, 24, kb, 4*h + 2, lane, vf + 4);
                    unsigned a4[4];
                    a4[0] = f2h2(sc[2*kb][0], sc[2*kb][1]);
                    a4[1] = f2h2(sc[2*kb][2], sc[2*kb][3]);
                    if (kb < 3) {
                        a4[2] = f2h2(sc[2*kb+1][0], sc[2*kb+1][1]);
                        a4[3] = f2h2(sc[2*kb+1][2], sc[2*kb+1][3]);
                    } else {
                        a4[2] = 0u; a4[3] = 0u;   // tokens 56-63: P = 0
                    }
                    #pragma unroll
                    for (int nv = 0; nv < 4; nv++) mmaf16(o[nv], a4, vf + 2*nv);
                }

                // normalize output rows, store to xs
                #pragma unroll
                for (int nv = 0; nv < 4; nv++) {
                    const int c0 = 32*h + nv*8 + 2*tig;
                    a_store(xs, q*16 + g,     c0, f2h2(o[nv][0]*inv0, o[nv][1]*inv0));
                    a_store(xs, q*16 + g + 8, c0, f2h2(o[nv][2]*inv1, o[nv][3]*inv1));
                }
            }
        }
        __syncthreads();

        // ---- output projection: 3 n-tiles per warp; B double-buffered ----
        {
            float acc[4][3][4];
            #pragma unroll
            for (int mt = 0; mt < 4; mt++)
                #pragma unroll
                for (int nt = 0; nt < 3; nt++)
                    #pragma unroll
                    for (int e = 0; e < 4; e++) acc[mt][nt][e] = 0.f;

            uint2 bb[3];
            #pragma unroll
            for (int nt = 0; nt < 3; nt++)
                bb[nt] = __ldg((const uint2*)g_Ph + (0*24 + w*3 + nt)*32 + lane);

            #pragma unroll
            for (int kk = 0; kk < NKB; kk++) {
                uint2 nb[3];
                if (kk + 1 < NKB) {
                    #pragma unroll
                    for (int nt = 0; nt < 3; nt++)
                        nb[nt] = __ldg((const uint2*)g_Ph + ((kk+1)*24 + w*3 + nt)*32 + lane);
                }
                unsigned a4[4][4];
                #pragma unroll
                for (int mt = 0; mt < 4; mt++) a_load(xs, kk, mt, lane, a4[mt]);
                #pragma unroll
                for (int nt = 0; nt < 3; nt++) {
                    unsigned bArr[2] = {bb[nt].x, bb[nt].y};
                    #pragma unroll
                    for (int mt = 0; mt < 4; mt++) mmaf16(acc[mt][nt], a4[mt], bArr);
                }
                #pragma unroll
                for (int nt = 0; nt < 3; nt++) bb[nt] = nb[nt];
            }

            float* og = out + (size_t)b * (NTOK*DIM);
            #pragma unroll
            for (int nt = 0; nt < 3; nt++) {
                const int j0 = (w*3 + nt)*8 + 2*tig;
                const float pb0 = __ldg(proj_b + j0);
                const float pb1 = __ldg(proj_b + j0 + 1);
                #pragma unroll
                for (int mt = 0; mt < 4; mt++) {
                    #pragma unroll
                    for (int hf = 0; hf < 2; hf++) {
                        const int row = mt*16 + g + hf*8;
                        if (row < NTOK) {
                            *(float2*)(og + row*DIM + j0) =
                                make_float2(acc[mt][nt][hf*2+0] + pb0,
                                            acc[mt][nt][hf*2+1] + pb1);
                        }
                    }
                }
            }
        }
        __syncthreads();   // proj reads of xs done before next window's x-load
    }
}

extern "C" void kernel_launch(void* const* d_in, const int* in_sizes, int n_in,
                              void* d_out, int out_size)
{
    const float* x          = (const float*)d_in[0];
    const float* mask       = (const float*)d_in[1];
    const float* qkv_w      = (const float*)d_in[2];
    const float* qkv_b      = (const float*)d_in[3];
    const float* proj_w     = (const float*)d_in[4];
    const float* proj_b     = (const float*)d_in[5];
    const float* bias_table = (const float*)d_in[6];
    const int*   rel_idx    = (const int*)d_in[7];
    float* out = (float*)d_out;

    prep_kernel<<<1024, 256>>>(qkv_w, proj_w, qkv_b, bias_table, rel_idx, mask);

    const int smem_bytes = SM_U * (int)sizeof(unsigned);
    cudaFuncSetAttribute(win_attn15,
                         cudaFuncAttributeMaxDynamicSharedMemorySize, smem_bytes);
    win_attn15<<<GRID, NTHR, smem_bytes>>>(x, proj_b, out);
}

// round 17
// speedup vs baseline: 1.0463x; 1.0463x over previous
#include <cuda_runtime.h>
#include <cuda_fp16.h>

#define DIM    192
#define HEADS  6
#define NTOK   49
#define NWIN   64
#define BMS    50
#define NTHR   256      // 8 warps, 3 CTAs/SM

#define NKB    12
#define XS_U   (NKB*4*128)     // 6144
#define KS_U   (NKB*7*64)      // 5376
#define VS_U   (4*24*64)       // 6144
#define SM_U   (XS_U + KS_U + VS_U)    // 17664 u32 = 70,656 B

__device__ unsigned g_Wh[12*72*32*2];            // qkv_w fp16, B-frag pair-packed (LDG.64)
__device__ unsigned g_Ph[12*24*32*2];            // proj_w fp16, B-frag pair-packed
__device__ float    g_bm[NWIN*HEADS*NTOK*BMS];   // bias+mask combined (fp32)

__device__ __forceinline__ unsigned f2h2(float x, float y) {
    __half2 h = __floats2half2_rn(x, y);
    return *(unsigned*)&h;
}

__device__ __forceinline__ void mmaf16(float d[4], const unsigned a[4], const unsigned b[2]) {
    asm volatile(
        "mma.sync.aligned.m16n8k16.row.col.f32.f16.f16.f32 "
        "{%0,%1,%2,%3}, {%4,%5,%6,%7}, {%8,%9}, {%0,%1,%2,%3};\n"
        : "+f"(d[0]), "+f"(d[1]), "+f"(d[2]), "+f"(d[3])
        : "r"(a[0]), "r"(a[1]), "r"(a[2]), "r"(a[3]), "r"(b[0]), "r"(b[1]));
}

__device__ __forceinline__ void ldsm_x4(unsigned a[4], const unsigned* p) {
    unsigned addr = (unsigned)__cvta_generic_to_shared(p);
    asm volatile("ldmatrix.sync.aligned.m8n8.x4.shared.b16 {%0,%1,%2,%3}, [%4];"
                 : "=r"(a[0]), "=r"(a[1]), "=r"(a[2]), "=r"(a[3]) : "r"(addr));
}
__device__ __forceinline__ void ldsm_x2(unsigned b[2], const unsigned* p) {
    unsigned addr = (unsigned)__cvta_generic_to_shared(p);
    asm volatile("ldmatrix.sync.aligned.m8n8.x2.shared.b16 {%0,%1}, [%2];"
                 : "=r"(b[0]), "=r"(b[1]) : "r"(addr));
}

// A block layout: unit u = ((col>>3)&1)*16 + (row&15), 16B contiguous in k.
__device__ __forceinline__ void a_load(const unsigned* base, int kblk, int mt, int lane, unsigned a[4]) {
    ldsm_x4(a, base + (kblk*4 + mt)*128 + lane*4);
}
__device__ __forceinline__ void a_store(unsigned* base, int row, int col, unsigned h2) {
    base[((col >> 4)*4 + (row >> 4))*128
         + (((col >> 3) & 1)*16 + (row & 15))*4 + ((col >> 1) & 3)] = h2;
}
// B block layout: unit u = ((k>>3)&1)*8 + (n&7).
__device__ __forceinline__ void b_load(const unsigned* base, int NT, int kblk, int nt, int lane, unsigned b[2]) {
    ldsm_x2(b, base + (kblk*NT + nt)*64 + (lane & 15)*4);
}
__device__ __forceinline__ void b_load2(const unsigned* base, int NT, int kblk, int nt, int lane, unsigned b4[4]) {
    ldsm_x4(b4, base + (kblk*NT + nt)*64 + lane*4);
}
__device__ __forceinline__ int b_slot(int NT, int kblk, int nt, int k, int n) {
    return (kblk*NT + nt)*64 + (((k >> 3) & 1)*8 + (n & 7))*4 + ((k >> 1) & 3);
}

// ---------------- prep kernel ----------------
__global__ void prep_kernel(const float* __restrict__ qkv_w,
                            const float* __restrict__ proj_w,
                            const float* __restrict__ bias_table,
                            const int*   __restrict__ rel_idx,
                            const float* __restrict__ mask)
{
    const int NWE = 96*576, NPE = 96*192, NBE = NWIN*HEADS*NTOK*NTOK;
    for (int idx = blockIdx.x*blockDim.x + threadIdx.x;
         idx < NWE + NPE + NBE; idx += gridDim.x*blockDim.x) {
        if (idx < NWE) {
            int kp = idx / 576, n = idx % 576;
            int k = 2*kp;
            int s = (((k >> 4)*72 + (n >> 3))*32 + ((n & 7)*4 + ((k >> 1) & 3)))*2
                    + ((k >> 3) & 1);
            g_Wh[s] = f2h2(qkv_w[n*192 + k], qkv_w[n*192 + k + 1]);
        } else if (idx < NWE + NPE) {
            int t = idx - NWE;
            int kp = t / 192, n = t % 192;
            int k = 2*kp;
            int s = (((k >> 4)*24 + (n >> 3))*32 + ((n & 7)*4 + ((k >> 1) & 3)))*2
                    + ((k >> 3) & 1);
            g_Ph[s] = f2h2(proj_w[n*192 + k], proj_w[n*192 + k + 1]);
        } else {
            int t = idx - NWE - NPE;
            int win = t / (HEADS*NTOK*NTOK);
            int r   = t % (HEADS*NTOK*NTOK);
            int h = r / (NTOK*NTOK);
            int e = r % (NTOK*NTOK);
            int i = e / NTOK, j = e % NTOK;
            g_bm[((win*HEADS + h)*NTOK + i)*BMS + j] =
                bias_table[rel_idx[e]*HEADS + h] + mask[win*(NTOK*NTOK) + e];
        }
    }
}

// ---------------- main kernel ----------------
__global__ __launch_bounds__(NTHR, 3)
void win_attn16(const float* __restrict__ x,
                const float* __restrict__ qkv_b,
                const float* __restrict__ proj_b,
                float* __restrict__ out)
{
    extern __shared__ unsigned smu[];
    unsigned* xs = smu;                 // A-pack: x -> Q (in place) -> attn-out (in place)
    unsigned* ks = xs + XS_U;           // B-pack K (tokens as n)
    unsigned* vs = ks + KS_U;           // B-pack V (tokens as k)

    const int tid  = threadIdx.x;
    const int w    = tid >> 5;
    const int lane = tid & 31;
    const int g    = lane >> 2;
    const int tig  = lane & 3;
    const int b    = blockIdx.x;
    const float scale = 0.17677669529663687f;

    // pad-zeroing merged with x-load (disjoint slots; one barrier orders all)
    for (int p = tid; p < 15*96; p += NTHR) {
        int row = 49 + p/96, cp = p%96;
        a_store(xs, row, 2*cp, 0u);
    }
    for (int p = tid; p < 768; p += NTHR) {
        int cblk = p >> 5;
        int rest = p & 31;
        vs[(3*24 + cblk)*64 + (8 + (rest >> 2))*4 + (rest & 3)] = 0u;
    }
    const float2* xg = (const float2*)(x + (size_t)b * (NTOK*DIM));
    for (int p = tid; p < NTOK*96; p += NTHR) {
        int row = p / 96, cp = p % 96;
        float2 v = xg[p];
        a_store(xs, row, 2*cp, f2h2(v.x, v.y));
    }
    __syncthreads();

    // ---- QKV GEMM: 3 passes (K, V, Q), 4mt x 3nt; B double-buffered ----
    for (int pass = 0; pass < 3; pass++) {
        const int t0 = (pass == 0) ? 24 + w*3 : (pass == 1) ? 48 + w*3 : w*3;
        float acc[4][3][4];
        #pragma unroll
        for (int mt = 0; mt < 4; mt++)
            #pragma unroll
            for (int j = 0; j < 3; j++)
                #pragma unroll
                for (int e = 0; e < 4; e++) acc[mt][j][e] = 0.f;

        uint2 bb[3];
        #pragma unroll
        for (int j = 0; j < 3; j++)
            bb[j] = __ldg((const uint2*)g_Wh + (0*72 + t0 + j)*32 + lane);

        #pragma unroll
        for (int kk = 0; kk < NKB; kk++) {
            uint2 nb[3];
            if (kk + 1 < NKB) {
                #pragma unroll
                for (int j = 0; j < 3; j++)
                    nb[j] = __ldg((const uint2*)g_Wh + ((kk+1)*72 + t0 + j)*32 + lane);
            }
            unsigned a4[4][4];
            #pragma unroll
            for (int mt = 0; mt < 4; mt++) a_load(xs, kk, mt, lane, a4[mt]);
            #pragma unroll
            for (int j = 0; j < 3; j++) {
                unsigned bArr[2] = {bb[j].x, bb[j].y};
                #pragma unroll
                for (int mt = 0; mt < 4; mt++) mmaf16(acc[mt][j], a4[mt], bArr);
            }
            #pragma unroll
            for (int j = 0; j < 3; j++) bb[j] = nb[j];
        }

        if (pass == 2) __syncthreads();   // all x reads done before Q overwrites xs

        #pragma unroll
        for (int j = 0; j < 3; j++) {
            const int j0 = (t0 + j)*8 + 2*tig;
            const float bj0 = __ldg(qkv_b + j0);
            const float bj1 = __ldg(qkv_b + j0 + 1);
            #pragma unroll
            for (int mt = 0; mt < 4; mt++) {
                #pragma unroll
                for (int hf = 0; hf < 2; hf++) {
                    float v0 = acc[mt][j][hf*2+0] + bj0;
                    float v1 = acc[mt][j][hf*2+1] + bj1;
                    if (pass == 0) {            // K: B[kdim][token]
                        const int token = mt*16 + g + 8*hf;
                        if (token < 56) {
                            const int kd = j0 - 192;
                            ks[b_slot(7, kd >> 4, token >> 3, kd, token)] = f2h2(v0, v1);
                        }
                    } else if (pass == 1) {     // V — pair-transpose via shfl
                        unsigned my = f2h2(v0, v1);
                        unsigned pt = __shfl_xor_sync(0xffffffffu, my, 4);
                        unsigned h2 = (g & 1) ? ((pt >> 16) | (my & 0xFFFF0000u))
                                              : ((my & 0xFFFFu) | (pt << 16));
                        const int n   = (j0 - 384) + (g & 1);
                        const int tok = mt*16 + g + 8*hf;
                        if (tok < 56)
                            vs[b_slot(24, tok >> 4, n >> 3, tok, n)] = h2;
                    } else {                    // Q (scaled) into xs in place
                        a_store(xs, mt*16 + g + 8*hf, j0, f2h2(v0*scale, v1*scale));
                    }
                }
            }
        }
    }
    __syncthreads();

    // ---- attention: 24 tasks (head x 16-row quarter), 3 per warp; rolled loop ----
    {
        #pragma unroll 1
        for (int it = 0; it < 3; it++) {
            const int t = w + it*8;
            const int h = t >> 2;
            const int q = t & 3;

            float sc[7][4];
            #pragma unroll
            for (int nt = 0; nt < 7; nt++)
                #pragma unroll
                for (int e = 0; e < 4; e++) sc[nt][e] = 0.f;

            // QK^T with paired-x4 K loads
            {
                const int kb0 = 2*h, kb1 = 2*h + 1;
                unsigned qa0[4], qa1[4];
                unsigned kf[7][2];
                a_load(xs, kb0, q, lane, qa0);
                b_load2(ks, 7, kb0, 0, lane, &kf[0][0]);
                b_load2(ks, 7, kb0, 2, lane, &kf[2][0]);
                b_load2(ks, 7, kb0, 4, lane, &kf[4][0]);
                b_load (ks, 7, kb0, 6, lane, kf[6]);
                a_load(xs, kb1, q, lane, qa1);
                #pragma unroll
                for (int nt = 0; nt < 7; nt++) mmaf16(sc[nt], qa0, kf[nt]);
                b_load2(ks, 7, kb1, 0, lane, &kf[0][0]);
                b_load2(ks, 7, kb1, 2, lane, &kf[2][0]);
                b_load2(ks, 7, kb1, 4, lane, &kf[4][0]);
                b_load (ks, 7, kb1, 6, lane, kf[6]);
                #pragma unroll
                for (int nt = 0; nt < 7; nt++) mmaf16(sc[nt], qa1, kf[nt]);
            }

            // add bias+mask, pad -> -1e30
            const float2* bmp = (const float2*)(g_bm
                              + (size_t)((b & (NWIN-1))*HEADS + h) * NTOK * BMS);
            const int i0 = q*16 + g;
            #pragma unroll
            for (int nt = 0; nt < 7; nt++) {
                const int j0 = nt*8 + 2*tig;
                float2 u0 = make_float2(0.f, 0.f), u1 = u0;
                if (i0 < NTOK && j0 < NTOK)   u0 = __ldg(bmp + (i0*BMS + j0)/2);
                if (i0+8 < NTOK && j0 < NTOK) u1 = __ldg(bmp + ((i0+8)*BMS + j0)/2);
                sc[nt][0] = (i0   < NTOK && j0   < NTOK) ? sc[nt][0] + u0.x : -1e30f;
                sc[nt][1] = (i0   < NTOK && j0+1 < NTOK) ? sc[nt][1] + u0.y : -1e30f;
                sc[nt][2] = (i0+8 < NTOK && j0   < NTOK) ? sc[nt][2] + u1.x : -1e30f;
                sc[nt][3] = (i0+8 < NTOK && j0+1 < NTOK) ? sc[nt][3] + u1.y : -1e30f;
            }

            // softmax (row owned by quad)
            #pragma unroll
            for (int hf = 0; hf < 2; hf++) {
                float m = -1e30f;
                #pragma unroll
                for (int nt = 0; nt < 7; nt++) {
                    m = fmaxf(m, sc[nt][hf*2+0]);
                    m = fmaxf(m, sc[nt][hf*2+1]);
                }
                m = fmaxf(m, __shfl_xor_sync(0xffffffffu, m, 1));
                m = fmaxf(m, __shfl_xor_sync(0xffffffffu, m, 2));
                float s = 0.f;
                #pragma unroll
                for (int nt = 0; nt < 7; nt++) {
                    float e0 = __expf(sc[nt][hf*2+0] - m);
                    float e1 = __expf(sc[nt][hf*2+1] - m);
                    sc[nt][hf*2+0] = e0; sc[nt][hf*2+1] = e1;
                    s += e0 + e1;
                }
                s += __shfl_xor_sync(0xffffffffu, s, 1);
                s += __shfl_xor_sync(0xffffffffu, s, 2);
                const float inv = __frcp_rn(s);
                #pragma unroll
                for (int nt = 0; nt < 7; nt++) {
                    sc[nt][hf*2+0] *= inv; sc[nt][hf*2+1] *= inv;
                }
            }

            // AV: P C-frags ARE the A-frags
            float o[4][4];
            #pragma unroll
            for (int nv = 0; nv < 4; nv++)
                #pragma unroll
                for (int e = 0; e < 4; e++) o[nv][e] = 0.f;

            #pragma unroll
            for (int kb = 0; kb < 4; kb++) {
                unsigned vf[8];
                b_load2(vs, 24, kb, 4*h + 0, lane, vf + 0);
                b_load2(vs, 24, kb, 4*h + 2, lane, vf + 4);
                unsigned a4[4];
                a4[0] = f2h2(sc[2*kb][0], sc[2*kb][1]);
                a4[1] = f2h2(sc[2*kb][2], sc[2*kb][3]);
                if (kb < 3) {
                    a4[2] = f2h2(sc[2*kb+1][0], sc[2*kb+1][1]);
                    a4[3] = f2h2(sc[2*kb+1][2], sc[2*kb+1][3]);
                } else {
                    a4[2] = 0u; a4[3] = 0u;   // tokens 56-63: P = 0
                }
                #pragma unroll
                for (int nv = 0; nv < 4; nv++) mmaf16(o[nv], a4, vf + 2*nv);
            }

            #pragma unroll
            for (int nv = 0; nv < 4; nv++) {
                const int c0 = 32*h + nv*8 + 2*tig;
                a_store(xs, q*16 + g,     c0, f2h2(o[nv][0], o[nv][1]));
                a_store(xs, q*16 + g + 8, c0, f2h2(o[nv][2], o[nv][3]));
            }
        }
    }
    __syncthreads();

    // ---- output projection: 3 n-tiles per warp; B double-buffered ----
    {
        float acc[4][3][4];
        #pragma unroll
        for (int mt = 0; mt < 4; mt++)
            #pragma unroll
            for (int nt = 0; nt < 3; nt++)
                #pragma unroll
                for (int e = 0; e < 4; e++) acc[mt][nt][e] = 0.f;

        uint2 bb[3];
        #pragma unroll
        for (int nt = 0; nt < 3; nt++)
            bb[nt] = __ldg((const uint2*)g_Ph + (0*24 + w*3 + nt)*32 + lane);

        #pragma unroll
        for (int kk = 0; kk < NKB; kk++) {
            uint2 nb[3];
            if (kk + 1 < NKB) {
                #pragma unroll
                for (int nt = 0; nt < 3; nt++)
                    nb[nt] = __ldg((const uint2*)g_Ph + ((kk+1)*24 + w*3 + nt)*32 + lane);
            }
            unsigned a4[4][4];
            #pragma unroll
            for (int mt = 0; mt < 4; mt++) a_load(xs, kk, mt, lane, a4[mt]);
            #pragma unroll
            for (int nt = 0; nt < 3; nt++) {
                unsigned bArr[2] = {bb[nt].x, bb[nt].y};
                #pragma unroll
                for (int mt = 0; mt < 4; mt++) mmaf16(acc[mt][nt], a4[mt], bArr);
            }
            #pragma unroll
            for (int nt = 0; nt < 3; nt++) bb[nt] = nb[nt];
        }

        float* og = out + (size_t)b * (NTOK*DIM);
        #pragma unroll
        for (int nt = 0; nt < 3; nt++) {
            const int j0 = (w*3 + nt)*8 + 2*tig;
            const float pb0 = __ldg(proj_b + j0);
            const float pb1 = __ldg(proj_b + j0 + 1);
            #pragma unroll
            for (int mt = 0; mt < 4; mt++) {
                #pragma unroll
                for (int hf = 0; hf < 2; hf++) {
                    const int row = mt*16 + g + hf*8;
                    if (row < NTOK) {
                        *(float2*)(og + row*DIM + j0) =
                            make_float2(acc[mt][nt][hf*2+0] + pb0,
                                        acc[mt][nt][hf*2+1] + pb1);
                    }
                }
            }
        }
    }
}

extern "C" void kernel_launch(void* const* d_in, const int* in_sizes, int n_in,
                              void* d_out, int out_size)
{
    const float* x          = (const float*)d_in[0];
    const float* mask       = (const float*)d_in[1];
    const float* qkv_w      = (const float*)d_in[2];
    const float* qkv_b      = (const float*)d_in[3];
    const float* proj_w     = (const float*)d_in[4];
    const float* proj_b     = (const float*)d_in[5];
    const float* bias_table = (const float*)d_in[6];
    const int*   rel_idx    = (const int*)d_in[7];
    float* out = (float*)d_out;

    prep_kernel<<<1024, 256>>>(qkv_w, proj_w, bias_table, rel_idx, mask);

    const int smem_bytes = SM_U * (int)sizeof(unsigned);
    cudaFuncSetAttribute(win_attn16,
                         cudaFuncAttributeMaxDynamicSharedMemorySize, smem_bytes);
    win_attn16<<<4096, NTHR, smem_bytes>>>(x, qkv_b, proj_b, out);
}